// round 9
// baseline (speedup 1.0000x reference)
#include <cuda_runtime.h>
#include <cuda_bf16.h>
#include <cstdint>

#define NHEAD 4
#define NEG_SLOPE 0.2f

// ---------------- scratch (allocation-free: __device__ globals) ----------------
__device__ float g_y   [11264 * NHEAD * 256];  // layer-0 aggregates (both levels)
__device__ float g_h   [11264 * 512];          // layer-0 outputs: h1 [0,10240), h0a [10240,11264)
__device__ float g_y2  [1024 * NHEAD * 512];   // layer-1 aggregates
__device__ float g_W2  [NHEAD * 512 * 256];    // folded weights
__device__ float g_part[NHEAD * 1024 * 256];   // per-head partial outputs

// ---------------- cp.async helpers ----------------
__device__ __forceinline__ uint32_t smem_u32(const void* p) {
    uint32_t a;
    asm("{ .reg .u64 t; cvta.to.shared.u64 t, %1; cvt.u32.u64 %0, t; }" : "=r"(a) : "l"(p));
    return a;
}
#define CP16(d, s)   asm volatile("cp.async.cg.shared.global [%0], [%1], 16;" :: "r"(d), "l"(s))
#define CP_COMMIT()  asm volatile("cp.async.commit_group;" ::: "memory")
#define CP_WAIT(n)   asm volatile("cp.async.wait_group %0;" :: "n"(n) : "memory")

// ---------------- bf16 split helpers ----------------
__device__ __forceinline__ uint32_t bfsplit2(float v0, float v1, uint32_t& lopk) {
    const unsigned short h0 = __bfloat16_as_ushort(__float2bfloat16_rn(v0));
    const unsigned short h1 = __bfloat16_as_ushort(__float2bfloat16_rn(v1));
    const float r0 = v0 - __bfloat162float(__ushort_as_bfloat16(h0));
    const float r1 = v1 - __bfloat162float(__ushort_as_bfloat16(h1));
    const unsigned short l0 = __bfloat16_as_ushort(__float2bfloat16_rn(r0));
    const unsigned short l1 = __bfloat16_as_ushort(__float2bfloat16_rn(r1));
    lopk = (uint32_t)l0 | ((uint32_t)l1 << 16);
    return (uint32_t)h0 | ((uint32_t)h1 << 16);
}

__device__ __forceinline__ void mma_bf16(float* d, const uint32_t* a, const uint32_t* b) {
    asm volatile(
        "mma.sync.aligned.m16n8k16.row.col.f32.bf16.bf16.f32 "
        "{%0,%1,%2,%3}, {%4,%5,%6,%7}, {%8,%9}, {%0,%1,%2,%3};"
        : "+f"(d[0]), "+f"(d[1]), "+f"(d[2]), "+f"(d[3])
        : "r"(a[0]), "r"(a[1]), "r"(a[2]), "r"(a[3]), "r"(b[0]), "r"(b[1]));
}

// ---------------- generalized split-bf16 HMMA GEMM (proven) ----------------
#define LRow 72

__global__ __launch_bounds__(256)
void gemm_hmma(const float* __restrict__ A, const float* __restrict__ W,
               float* __restrict__ C,
               int K, int lda, long aHeadStride,
               int ldw, long wHeadStride,
               int ldc, long cHeadStride)
{
    extern __shared__ unsigned short smem[];
    unsigned short* AsH = smem;
    unsigned short* AsL = smem + 64 * LRow;
    unsigned short* BsH = smem + 2 * 64 * LRow;
    unsigned short* BsL = BsH + 128 * LRow;

    const int tid  = threadIdx.x;
    const int wid  = tid >> 5;
    const int lane = tid & 31;
    const int g    = lane >> 2;
    const int t    = lane & 3;
    const int wm   = (wid >> 2) * 32;
    const int wn   = (wid & 3) * 32;

    const int m0 = blockIdx.x * 64;
    const int bn = blockIdx.y * 128;
    const int h  = blockIdx.z;
    const float* Ah = A + (long)h * aHeadStride;
    const float* Wh = W + (long)h * wHeadStride;
    float*       Ch = C + (long)h * cHeadStride;

    float acc[2][4][4];
    #pragma unroll
    for (int i = 0; i < 2; i++)
        #pragma unroll
        for (int j = 0; j < 4; j++)
            #pragma unroll
            for (int q = 0; q < 4; q++) acc[i][j][q] = 0.f;

    const int nChunks = K >> 6;
    for (int s = 0; s < nChunks; s++) {
        const int k0 = s * 64;
        __syncthreads();

        #pragma unroll
        for (int i = 0; i < 4; i++) {
            const int idx = tid + i * 256;
            const int row = idx >> 4;
            const int c4  = (idx & 15) * 4;
            const float4 v = *(const float4*)(Ah + (long)(m0 + row) * lda + k0 + c4);
            uint32_t lo0, lo1;
            const uint32_t hi0 = bfsplit2(v.x, v.y, lo0);
            const uint32_t hi1 = bfsplit2(v.z, v.w, lo1);
            *(uint2*)&AsH[row * LRow + c4] = make_uint2(hi0, hi1);
            *(uint2*)&AsL[row * LRow + c4] = make_uint2(lo0, lo1);
        }
        {
            const int n  = tid & 127;
            const int kb = (tid >> 7) * 32;
            #pragma unroll
            for (int jq = 0; jq < 4; jq++) {
                uint32_t hi[4], lo[4];
                #pragma unroll
                for (int j2 = 0; j2 < 4; j2++) {
                    const int k = k0 + kb + jq * 8 + j2 * 2;
                    const float v0 = Wh[(long)k * ldw + bn + n];
                    const float v1 = Wh[(long)(k + 1) * ldw + bn + n];
                    hi[j2] = bfsplit2(v0, v1, lo[j2]);
                }
                *(uint4*)&BsH[n * LRow + kb + jq * 8] = make_uint4(hi[0], hi[1], hi[2], hi[3]);
                *(uint4*)&BsL[n * LRow + kb + jq * 8] = make_uint4(lo[0], lo[1], lo[2], lo[3]);
            }
        }
        __syncthreads();

        #pragma unroll
        for (int kk = 0; kk < 64; kk += 16) {
            uint32_t ah[2][4], al[2][4];
            #pragma unroll
            for (int mt = 0; mt < 2; mt++) {
                const int r = wm + mt * 16;
                const int ca = kk + t * 2;
                ah[mt][0] = *(const uint32_t*)&AsH[(r + g)     * LRow + ca];
                ah[mt][1] = *(const uint32_t*)&AsH[(r + 8 + g) * LRow + ca];
                ah[mt][2] = *(const uint32_t*)&AsH[(r + g)     * LRow + ca + 8];
                ah[mt][3] = *(const uint32_t*)&AsH[(r + 8 + g) * LRow + ca + 8];
                al[mt][0] = *(const uint32_t*)&AsL[(r + g)     * LRow + ca];
                al[mt][1] = *(const uint32_t*)&AsL[(r + 8 + g) * LRow + ca];
                al[mt][2] = *(const uint32_t*)&AsL[(r + g)     * LRow + ca + 8];
                al[mt][3] = *(const uint32_t*)&AsL[(r + 8 + g) * LRow + ca + 8];
            }
            uint32_t bh[4][2], bl[4][2];
            #pragma unroll
            for (int nt = 0; nt < 4; nt++) {
                const int n = wn + nt * 8 + g;
                const int cb = kk + t * 2;
                bh[nt][0] = *(const uint32_t*)&BsH[n * LRow + cb];
                bh[nt][1] = *(const uint32_t*)&BsH[n * LRow + cb + 8];
                bl[nt][0] = *(const uint32_t*)&BsL[n * LRow + cb];
                bl[nt][1] = *(const uint32_t*)&BsL[n * LRow + cb + 8];
            }
            #pragma unroll
            for (int mt = 0; mt < 2; mt++)
                #pragma unroll
                for (int nt = 0; nt < 4; nt++) {
                    mma_bf16(acc[mt][nt], ah[mt], bh[nt]);
                    mma_bf16(acc[mt][nt], ah[mt], bl[nt]);
                    mma_bf16(acc[mt][nt], al[mt], bh[nt]);
                }
        }
    }

    #pragma unroll
    for (int mt = 0; mt < 2; mt++)
        #pragma unroll
        for (int nt = 0; nt < 4; nt++) {
            const int r  = m0 + wm + mt * 16 + g;
            const int cc = bn + wn + nt * 8 + t * 2;
            *(float2*)(Ch + (long)r * ldc + cc)       = make_float2(acc[mt][nt][0], acc[mt][nt][1]);
            *(float2*)(Ch + (long)(r + 8) * ldc + cc) = make_float2(acc[mt][nt][2], acc[mt][nt][3]);
        }
}

// ---------------- pipelined fused attention + aggregation ----------------
// Each CTA processes IPC consecutive items with double-buffered cp.async staging:
// while item i is computed from buf[i&1], item i+1 streams into buf[(i+1)&1].
template <int F>
__global__ __launch_bounds__(256)
void gat_attn_pipe(const float* __restrict__ xsA, const float* __restrict__ xnA, int SA, int nA,
                   const float* __restrict__ xsB, const float* __restrict__ xnB, int SB, int nTot,
                   const float* __restrict__ a_self, const float* __restrict__ a_neigh,
                   float* __restrict__ y, int IPC)
{
    constexpr int RCAP = (F == 256) ? 26 : 11;
    extern __shared__ float sm[];
    float* bufs   = sm;                       // 2 x RCAP*F
    float* slog   = sm + 2 * RCAP * F;        // RCAP*4
    float* slself = slog + RCAP * 4;          // 4

    const int tid = threadIdx.x;
    const int w = tid >> 5, l = tid & 31;
    const int base = blockIdx.x * IPC;

    auto issue = [&](int item, int buf) {
        if (item >= nTot) return;
        const float* xs; const float* xn; int S;
        if (item < nA) { xs = xsA + (long)item * F; xn = xnA + (long)item * SA * F; S = SA; }
        else { int b = item - nA; xs = xsB + (long)b * F; xn = xnB + (long)b * SB * F; S = SB; }
        const uint32_t sx_u = smem_u32(bufs + buf * RCAP * F);
        const float4* s4 = (const float4*)xs;
        for (int i = tid; i < F / 4; i += 256) CP16(sx_u + i * 16, s4 + i);
        const float4* n4 = (const float4*)xn;
        for (int i = tid; i < S * F / 4; i += 256) CP16(sx_u + (F / 4 + i) * 16, n4 + i);
    };

    issue(base, 0);
    CP_COMMIT();

    for (int it = 0; it < IPC; it++) {
        const int item = base + it;
        const bool more = (it + 1 < IPC);
        if (more) { issue(item + 1, (it + 1) & 1); CP_COMMIT(); }
        if (more) CP_WAIT(1); else CP_WAIT(0);
        __syncthreads();

        if (item < nTot) {
            const int S = (item < nA) ? SA : SB;
            float* sx = bufs + (it & 1) * RCAP * F;
            float* yo = y + (long)item * NHEAD * F;

            // self logits (warp 0, from staged smem row 0; a_self L2-hot)
            if (w == 0) {
                float sl[4] = {0.f, 0.f, 0.f, 0.f};
                for (int c = 0; c < F / 256; c++) {
                    #pragma unroll
                    for (int fi = 0; fi < 8; fi++) {
                        const int f = c * 256 + l + fi * 32;
                        const float xv = sx[f];
                        sl[0] += xv * a_self[0 * F + f];
                        sl[1] += xv * a_self[1 * F + f];
                        sl[2] += xv * a_self[2 * F + f];
                        sl[3] += xv * a_self[3 * F + f];
                    }
                }
                #pragma unroll
                for (int h = 0; h < 4; h++) {
                    float v = sl[h];
                    #pragma unroll
                    for (int o = 16; o; o >>= 1) v += __shfl_down_sync(0xffffffffu, v, o);
                    if (l == 0) slself[h] = v;
                }
            }
            __syncthreads();

            // neighbor-side logits (a_neigh in registers)
            {
                float lg[4][4] = {};
                for (int c = 0; c < F / 256; c++) {
                    float avn[4][8];
                    #pragma unroll
                    for (int h = 0; h < 4; h++)
                        #pragma unroll
                        for (int fi = 0; fi < 8; fi++)
                            avn[h][fi] = a_neigh[h * F + c * 256 + l + fi * 32];
                    #pragma unroll
                    for (int ti = 0; ti < 4; ti++) {
                        const int tt = w + ti * 8;
                        if (tt <= S) {
                            const float* row = sx + tt * F + c * 256;
                            #pragma unroll
                            for (int fi = 0; fi < 8; fi++) {
                                const float xv = row[l + fi * 32];
                                lg[ti][0] += xv * avn[0][fi];
                                lg[ti][1] += xv * avn[1][fi];
                                lg[ti][2] += xv * avn[2][fi];
                                lg[ti][3] += xv * avn[3][fi];
                            }
                        }
                    }
                }
                #pragma unroll
                for (int ti = 0; ti < 4; ti++) {
                    const int tt = w + ti * 8;
                    #pragma unroll
                    for (int h = 0; h < 4; h++) {
                        float v = lg[ti][h];
                        #pragma unroll
                        for (int o = 16; o; o >>= 1) v += __shfl_down_sync(0xffffffffu, v, o);
                        if (l == 0 && tt <= S) slog[tt * 4 + h] = v;
                    }
                }
            }
            __syncthreads();

            // leaky-relu + softmax over S+1 (one warp, lane = s)
            if (tid < 32) {
                const bool act = (l <= S);
                float z[4];
                #pragma unroll
                for (int h = 0; h < 4; h++) {
                    float v = act ? (slself[h] + slog[l * 4 + h]) : -1e30f;
                    z[h] = (v >= 0.f) ? v : NEG_SLOPE * v;
                }
                #pragma unroll
                for (int h = 0; h < 4; h++) {
                    float m = z[h];
                    #pragma unroll
                    for (int o = 16; o; o >>= 1) m = fmaxf(m, __shfl_xor_sync(0xffffffffu, m, o));
                    const float ev = act ? __expf(z[h] - m) : 0.f;
                    float s = ev;
                    #pragma unroll
                    for (int o = 16; o; o >>= 1) s += __shfl_xor_sync(0xffffffffu, s, o);
                    if (act) slog[l * 4 + h] = ev / s;
                }
            }
            __syncthreads();

            // aggregation: y[h][f] = sum_s attn[s][h] * x_all[s][f]
            for (int f = tid; f < F; f += 256) {
                float a0 = 0.f, a1 = 0.f, a2 = 0.f, a3 = 0.f;
                for (int s = 0; s <= S; s++) {
                    const float xv = sx[s * F + f];
                    const float4 at = *(const float4*)(slog + s * 4);
                    a0 += at.x * xv; a1 += at.y * xv; a2 += at.z * xv; a3 += at.w * xv;
                }
                yo[0 * F + f] = a0; yo[1 * F + f] = a1; yo[2 * F + f] = a2; yo[3 * F + f] = a3;
            }
        }
        __syncthreads();   // buffer free for next prefetch overwrite
    }
}

// ---------------- 4-way partial reduce ----------------
__global__ void reduce4(const float4* __restrict__ p, float4* __restrict__ out, int n4)
{
    const int i = blockIdx.x * blockDim.x + threadIdx.x;
    if (i < n4) {
        float4 a = p[i], b = p[i + n4], c = p[i + 2 * n4], d = p[i + 3 * n4];
        out[i] = make_float4(a.x + b.x + c.x + d.x, a.y + b.y + c.y + d.y,
                             a.z + b.z + c.z + d.z, a.w + b.w + c.w + d.w);
    }
}

// ---------------- launch ----------------
static float* sym_addr(const void* symbol)
{
    void* p = nullptr;
    cudaGetSymbolAddress(&p, symbol);
    return (float*)p;
}

extern "C" void kernel_launch(void* const* d_in, const int* in_sizes, int n_in,
                              void* d_out, int out_size)
{
    const float* x0  = (const float*)d_in[0];
    const float* x1  = (const float*)d_in[1];
    const float* x2  = (const float*)d_in[2];
    const float* w0  = (const float*)d_in[3];
    const float* a0s = (const float*)d_in[4];
    const float* a0n = (const float*)d_in[5];
    const float* w1  = (const float*)d_in[6];
    const float* a1s = (const float*)d_in[7];
    const float* a1n = (const float*)d_in[8];
    const float* fcw = (const float*)d_in[9];
    float* out = (float*)d_out;

    const int Bn   = in_sizes[0] / 256;        // 1024
    const int nA   = Bn * 10;                  // 10240
    const int nTot = nA + Bn;                  // 11264

    float* y    = sym_addr(g_y);
    float* hb   = sym_addr(g_h);
    float* y2   = sym_addr(g_y2);
    float* W2   = sym_addr(g_W2);
    float* part = sym_addr(g_part);

    const int smemB = (2 * 64 + 2 * 128) * LRow * 2;   // 55296 bytes
    cudaFuncSetAttribute(gemm_hmma, cudaFuncAttributeMaxDynamicSharedMemorySize, smemB);

    const int smemA0 = (2 * 26 * 256 + 26 * 4 + 8) * 4;   // ~53.7 KB
    const int smemA1 = (2 * 11 * 512 + 11 * 4 + 8) * 4;   // ~45.3 KB
    cudaFuncSetAttribute(gat_attn_pipe<256>, cudaFuncAttributeMaxDynamicSharedMemorySize, smemA0);
    cudaFuncSetAttribute(gat_attn_pipe<512>, cudaFuncAttributeMaxDynamicSharedMemorySize, smemA1);

    // ---- W2 precompute ----
    gemm_hmma<<<dim3(8, 2, NHEAD), 256, smemB>>>(
        w1, fcw, W2, 128,
        128, (long)512 * 128,
        256, (long)128 * 256,
        256, (long)512 * 256);

    // ---- layer-0 attention, both levels, pipelined IPC=8 ----
    {
        const int IPC = 8;
        gat_attn_pipe<256><<<(nTot + IPC - 1) / IPC, 256, smemA0>>>(
            x1, x2, 25, nA, x0, x1, 10, nTot, a0s, a0n, y, IPC);
    }

    // ---- layer-0 projection: hb = y @ w0 per head ----
    gemm_hmma<<<dim3(nTot / 64, 1, NHEAD), 256, smemB>>>(
        y, w0, hb, 256,
        NHEAD * 256, 256,
        128, (long)256 * 128,
        512, 128);

    // ---- layer-1 attention, pipelined IPC=2 ----
    {
        const int IPC = 2;
        gat_attn_pipe<512><<<(Bn + IPC - 1) / IPC, 256, smemA1>>>(
            hb + (long)nA * 512, hb, 10, Bn,
            hb + (long)nA * 512, hb, 10, Bn,
            a1s, a1n, y2, IPC);
    }

    // ---- folded back-end: part[h] = y2[:,h,:] @ W2[h] ----
    gemm_hmma<<<dim3(Bn / 64, 2, NHEAD), 256, smemB>>>(
        y2, W2, part, 512,
        NHEAD * 512, 512,
        256, (long)512 * 256,
        256, (long)Bn * 256);

    // ---- out = sum over heads ----
    const int n4 = Bn * 256 / 4;
    reduce4<<<(n4 + 255) / 256, 256>>>((const float4*)part, (float4*)out, n4);
}

// round 10
// speedup vs baseline: 1.2019x; 1.2019x over previous
#include <cuda_runtime.h>
#include <cuda_bf16.h>
#include <cstdint>

#define NHEAD 4
#define NEG_SLOPE 0.2f

// ---------------- scratch (allocation-free: __device__ globals) ----------------
__device__ __nv_bfloat16 g_yh  [11264 * 1024];   // layer-0 aggregates, bf16 hi
__device__ __nv_bfloat16 g_yl  [11264 * 1024];   // layer-0 aggregates, bf16 lo
__device__ float         g_h   [11264 * 512];    // layer-0 outputs (f32)
__device__ __nv_bfloat16 g_y2h [1024 * 2048];    // layer-1 aggregates hi
__device__ __nv_bfloat16 g_y2l [1024 * 2048];    // layer-1 aggregates lo
__device__ float         g_W2  [NHEAD * 512 * 256];   // folded weights (f32, from fold GEMM)
__device__ __nv_bfloat16 g_Wt2h[NHEAD * 256 * 512];   // W2 transposed+split
__device__ __nv_bfloat16 g_Wt2l[NHEAD * 256 * 512];
__device__ __nv_bfloat16 g_Wt0h[NHEAD * 128 * 256];   // w0 transposed+split
__device__ __nv_bfloat16 g_Wt0l[NHEAD * 128 * 256];
__device__ float         g_part[NHEAD * 1024 * 256];  // per-head partial outputs

// ---------------- helpers ----------------
__device__ __forceinline__ uint32_t smem_u32(const void* p) {
    uint32_t a;
    asm("{ .reg .u64 t; cvta.to.shared.u64 t, %1; cvt.u32.u64 %0, t; }" : "=r"(a) : "l"(p));
    return a;
}
#define CP16(d, s)  asm volatile("cp.async.cg.shared.global [%0], [%1], 16;" :: "r"(d), "l"(s))
#define CP_COMMIT() asm volatile("cp.async.commit_group;" ::: "memory")
#define CP_WAIT0()  asm volatile("cp.async.wait_group 0;" ::: "memory")

__device__ __forceinline__ uint32_t bfsplit2(float v0, float v1, uint32_t& lopk) {
    const unsigned short h0 = __bfloat16_as_ushort(__float2bfloat16_rn(v0));
    const unsigned short h1 = __bfloat16_as_ushort(__float2bfloat16_rn(v1));
    const float r0 = v0 - __bfloat162float(__ushort_as_bfloat16(h0));
    const float r1 = v1 - __bfloat162float(__ushort_as_bfloat16(h1));
    const unsigned short l0 = __bfloat16_as_ushort(__float2bfloat16_rn(r0));
    const unsigned short l1 = __bfloat16_as_ushort(__float2bfloat16_rn(r1));
    lopk = (uint32_t)l0 | ((uint32_t)l1 << 16);
    return (uint32_t)h0 | ((uint32_t)h1 << 16);
}

__device__ __forceinline__ void mma_bf16(float* d, const uint32_t* a, const uint32_t* b) {
    asm volatile(
        "mma.sync.aligned.m16n8k16.row.col.f32.bf16.bf16.f32 "
        "{%0,%1,%2,%3}, {%4,%5,%6,%7}, {%8,%9}, {%0,%1,%2,%3};"
        : "+f"(d[0]), "+f"(d[1]), "+f"(d[2]), "+f"(d[3])
        : "r"(a[0]), "r"(a[1]), "r"(a[2]), "r"(a[3]), "r"(b[0]), "r"(b[1]));
}

#define LRow 72

// ---------------- f32-input split-bf16 HMMA GEMM (fold only; round-8 proven) ----------------
__global__ __launch_bounds__(256)
void gemm_hmma(const float* __restrict__ A, const float* __restrict__ W,
               float* __restrict__ C,
               int K, int lda, long aHeadStride,
               int ldw, long wHeadStride,
               int ldc, long cHeadStride)
{
    extern __shared__ unsigned short smem[];
    unsigned short* AsH = smem;
    unsigned short* AsL = smem + 64 * LRow;
    unsigned short* BsH = smem + 2 * 64 * LRow;
    unsigned short* BsL = BsH + 128 * LRow;

    const int tid  = threadIdx.x;
    const int wid  = tid >> 5;
    const int lane = tid & 31;
    const int g    = lane >> 2;
    const int t    = lane & 3;
    const int wm   = (wid >> 2) * 32;
    const int wn   = (wid & 3) * 32;

    const int m0 = blockIdx.x * 64;
    const int bn = blockIdx.y * 128;
    const int h  = blockIdx.z;
    const float* Ah = A + (long)h * aHeadStride;
    const float* Wh = W + (long)h * wHeadStride;
    float*       Ch = C + (long)h * cHeadStride;

    float acc[2][4][4];
    #pragma unroll
    for (int i = 0; i < 2; i++)
        #pragma unroll
        for (int j = 0; j < 4; j++)
            #pragma unroll
            for (int q = 0; q < 4; q++) acc[i][j][q] = 0.f;

    const int nChunks = K >> 6;
    for (int s = 0; s < nChunks; s++) {
        const int k0 = s * 64;
        __syncthreads();

        #pragma unroll
        for (int i = 0; i < 4; i++) {
            const int idx = tid + i * 256;
            const int row = idx >> 4;
            const int c4  = (idx & 15) * 4;
            const float4 v = *(const float4*)(Ah + (long)(m0 + row) * lda + k0 + c4);
            uint32_t lo0, lo1;
            const uint32_t hi0 = bfsplit2(v.x, v.y, lo0);
            const uint32_t hi1 = bfsplit2(v.z, v.w, lo1);
            *(uint2*)&AsH[row * LRow + c4] = make_uint2(hi0, hi1);
            *(uint2*)&AsL[row * LRow + c4] = make_uint2(lo0, lo1);
        }
        {
            const int n  = tid & 127;
            const int kb = (tid >> 7) * 32;
            #pragma unroll
            for (int jq = 0; jq < 4; jq++) {
                uint32_t hi[4], lo[4];
                #pragma unroll
                for (int j2 = 0; j2 < 4; j2++) {
                    const int k = k0 + kb + jq * 8 + j2 * 2;
                    const float v0 = Wh[(long)k * ldw + bn + n];
                    const float v1 = Wh[(long)(k + 1) * ldw + bn + n];
                    hi[j2] = bfsplit2(v0, v1, lo[j2]);
                }
                *(uint4*)&BsH[n * LRow + kb + jq * 8] = make_uint4(hi[0], hi[1], hi[2], hi[3]);
                *(uint4*)&BsL[n * LRow + kb + jq * 8] = make_uint4(lo[0], lo[1], lo[2], lo[3]);
            }
        }
        __syncthreads();

        #pragma unroll
        for (int kk = 0; kk < 64; kk += 16) {
            uint32_t ah[2][4], al[2][4];
            #pragma unroll
            for (int mt = 0; mt < 2; mt++) {
                const int r = wm + mt * 16;
                const int ca = kk + t * 2;
                ah[mt][0] = *(const uint32_t*)&AsH[(r + g)     * LRow + ca];
                ah[mt][1] = *(const uint32_t*)&AsH[(r + 8 + g) * LRow + ca];
                ah[mt][2] = *(const uint32_t*)&AsH[(r + g)     * LRow + ca + 8];
                ah[mt][3] = *(const uint32_t*)&AsH[(r + 8 + g) * LRow + ca + 8];
                al[mt][0] = *(const uint32_t*)&AsL[(r + g)     * LRow + ca];
                al[mt][1] = *(const uint32_t*)&AsL[(r + 8 + g) * LRow + ca];
                al[mt][2] = *(const uint32_t*)&AsL[(r + g)     * LRow + ca + 8];
                al[mt][3] = *(const uint32_t*)&AsL[(r + 8 + g) * LRow + ca + 8];
            }
            uint32_t bh[4][2], bl[4][2];
            #pragma unroll
            for (int nt = 0; nt < 4; nt++) {
                const int n = wn + nt * 8 + g;
                const int cb = kk + t * 2;
                bh[nt][0] = *(const uint32_t*)&BsH[n * LRow + cb];
                bh[nt][1] = *(const uint32_t*)&BsH[n * LRow + cb + 8];
                bl[nt][0] = *(const uint32_t*)&BsL[n * LRow + cb];
                bl[nt][1] = *(const uint32_t*)&BsL[n * LRow + cb + 8];
            }
            #pragma unroll
            for (int mt = 0; mt < 2; mt++)
                #pragma unroll
                for (int nt = 0; nt < 4; nt++) {
                    mma_bf16(acc[mt][nt], ah[mt], bh[nt]);
                    mma_bf16(acc[mt][nt], ah[mt], bl[nt]);
                    mma_bf16(acc[mt][nt], al[mt], bh[nt]);
                }
        }
    }

    #pragma unroll
    for (int mt = 0; mt < 2; mt++)
        #pragma unroll
        for (int nt = 0; nt < 4; nt++) {
            const int r  = m0 + wm + mt * 16 + g;
            const int cc = bn + wn + nt * 8 + t * 2;
            *(float2*)(Ch + (long)r * ldc + cc)       = make_float2(acc[mt][nt][0], acc[mt][nt][1]);
            *(float2*)(Ch + (long)(r + 8) * ldc + cc) = make_float2(acc[mt][nt][2], acc[mt][nt][3]);
        }
}

// ---------------- pre-split bf16 HMMA GEMM with register prefetch ----------------
// A: hi/lo bf16 [m][lda] (+h*aHeadStride). W: hi/lo bf16 transposed [h][n][K].
// C f32: Ch = C + h*cHeadStride, element [m][bn+n], ldc.
__global__ __launch_bounds__(256)
void gemm_hmma_pre(const __nv_bfloat16* __restrict__ Ahg, const __nv_bfloat16* __restrict__ Alg,
                   const __nv_bfloat16* __restrict__ Whg, const __nv_bfloat16* __restrict__ Wlg,
                   float* __restrict__ C,
                   int K, int lda, long aHeadStride, long wHeadStride,
                   int ldc, long cHeadStride)
{
    extern __shared__ unsigned short smem[];
    unsigned short* AsH = smem;
    unsigned short* AsL = smem + 64 * LRow;
    unsigned short* BsH = smem + 2 * 64 * LRow;
    unsigned short* BsL = BsH + 128 * LRow;

    const int tid  = threadIdx.x;
    const int wid  = tid >> 5;
    const int lane = tid & 31;
    const int g    = lane >> 2;
    const int t    = lane & 3;
    const int wm   = (wid >> 2) * 32;
    const int wn   = (wid & 3) * 32;

    const int m0 = blockIdx.x * 64;
    const int bn = blockIdx.y * 128;
    const int h  = blockIdx.z;
    const unsigned short* pAh = (const unsigned short*)Ahg + (long)h * aHeadStride;
    const unsigned short* pAl = (const unsigned short*)Alg + (long)h * aHeadStride;
    const unsigned short* pWh = (const unsigned short*)Whg + (long)h * wHeadStride + (long)bn * K;
    const unsigned short* pWl = (const unsigned short*)Wlg + (long)h * wHeadStride + (long)bn * K;
    float* Ch = C + (long)h * cHeadStride;

    float acc[2][4][4];
    #pragma unroll
    for (int i = 0; i < 2; i++)
        #pragma unroll
        for (int j = 0; j < 4; j++)
            #pragma unroll
            for (int q = 0; q < 4; q++) acc[i][j][q] = 0.f;

    // staging indices: A (2 uint4/thread), B (4 uint4/thread); 8 shorts per uint4
    const int arow = tid >> 3,          ac8 = (tid & 7) * 8;          // +i*32 rows
    const int brow = tid >> 3,          bc8 = (tid & 7) * 8;          // +i*32 rows

    uint4 ra[2], rl[2], rb[4], rbl[4];

    auto ldg = [&](int k0) {
        #pragma unroll
        for (int i = 0; i < 2; i++) {
            const long off = (long)(m0 + arow + i * 32) * lda + k0 + ac8;
            ra[i] = *(const uint4*)(pAh + off);
            rl[i] = *(const uint4*)(pAl + off);
        }
        #pragma unroll
        for (int i = 0; i < 4; i++) {
            const long off = (long)(brow + i * 32) * K + k0 + bc8;
            rb[i]  = *(const uint4*)(pWh + off);
            rbl[i] = *(const uint4*)(pWl + off);
        }
    };
    auto sts = [&]() {
        #pragma unroll
        for (int i = 0; i < 2; i++) {
            const int o = (arow + i * 32) * LRow + ac8;
            *(uint2*)&AsH[o]     = make_uint2(ra[i].x, ra[i].y);
            *(uint2*)&AsH[o + 4] = make_uint2(ra[i].z, ra[i].w);
            *(uint2*)&AsL[o]     = make_uint2(rl[i].x, rl[i].y);
            *(uint2*)&AsL[o + 4] = make_uint2(rl[i].z, rl[i].w);
        }
        #pragma unroll
        for (int i = 0; i < 4; i++) {
            const int o = (brow + i * 32) * LRow + bc8;
            *(uint2*)&BsH[o]     = make_uint2(rb[i].x, rb[i].y);
            *(uint2*)&BsH[o + 4] = make_uint2(rb[i].z, rb[i].w);
            *(uint2*)&BsL[o]     = make_uint2(rbl[i].x, rbl[i].y);
            *(uint2*)&BsL[o + 4] = make_uint2(rbl[i].z, rbl[i].w);
        }
    };
    auto compute = [&]() {
        #pragma unroll
        for (int kk = 0; kk < 64; kk += 16) {
            uint32_t ah[2][4], al[2][4];
            #pragma unroll
            for (int mt = 0; mt < 2; mt++) {
                const int r = wm + mt * 16;
                const int ca = kk + t * 2;
                ah[mt][0] = *(const uint32_t*)&AsH[(r + g)     * LRow + ca];
                ah[mt][1] = *(const uint32_t*)&AsH[(r + 8 + g) * LRow + ca];
                ah[mt][2] = *(const uint32_t*)&AsH[(r + g)     * LRow + ca + 8];
                ah[mt][3] = *(const uint32_t*)&AsH[(r + 8 + g) * LRow + ca + 8];
                al[mt][0] = *(const uint32_t*)&AsL[(r + g)     * LRow + ca];
                al[mt][1] = *(const uint32_t*)&AsL[(r + 8 + g) * LRow + ca];
                al[mt][2] = *(const uint32_t*)&AsL[(r + g)     * LRow + ca + 8];
                al[mt][3] = *(const uint32_t*)&AsL[(r + 8 + g) * LRow + ca + 8];
            }
            uint32_t bh[4][2], bl[4][2];
            #pragma unroll
            for (int nt = 0; nt < 4; nt++) {
                const int n = wn + nt * 8 + g;
                const int cb = kk + t * 2;
                bh[nt][0] = *(const uint32_t*)&BsH[n * LRow + cb];
                bh[nt][1] = *(const uint32_t*)&BsH[n * LRow + cb + 8];
                bl[nt][0] = *(const uint32_t*)&BsL[n * LRow + cb];
                bl[nt][1] = *(const uint32_t*)&BsL[n * LRow + cb + 8];
            }
            #pragma unroll
            for (int mt = 0; mt < 2; mt++)
                #pragma unroll
                for (int nt = 0; nt < 4; nt++) {
                    mma_bf16(acc[mt][nt], ah[mt], bh[nt]);
                    mma_bf16(acc[mt][nt], ah[mt], bl[nt]);
                    mma_bf16(acc[mt][nt], al[mt], bh[nt]);
                }
        }
    };

    const int nChunks = K >> 6;
    ldg(0);
    sts();
    __syncthreads();
    for (int s = 0; s < nChunks; s++) {
        if (s + 1 < nChunks) ldg((s + 1) * 64);   // prefetch overlaps compute
        compute();
        if (s + 1 < nChunks) {
            __syncthreads();
            sts();
            __syncthreads();
        }
    }

    #pragma unroll
    for (int mt = 0; mt < 2; mt++)
        #pragma unroll
        for (int nt = 0; nt < 4; nt++) {
            const int r  = m0 + wm + mt * 16 + g;
            const int cc = bn + wn + nt * 8 + t * 2;
            *(float2*)(Ch + (long)r * ldc + cc)       = make_float2(acc[mt][nt][0], acc[mt][nt][1]);
            *(float2*)(Ch + (long)(r + 8) * ldc + cc) = make_float2(acc[mt][nt][2], acc[mt][nt][3]);
        }
}

// ---------------- tiled transpose + split: in[h][K][N] f32 -> out[h][N][K] bf16 hi/lo ----------------
__global__ void transpose_split(const float* __restrict__ in,
                                __nv_bfloat16* __restrict__ outh,
                                __nv_bfloat16* __restrict__ outl,
                                int K, int N)
{
    __shared__ float tile[32][33];
    const int h  = blockIdx.z;
    const int k0 = blockIdx.x * 32;
    const int n0 = blockIdx.y * 32;
    const int tx = threadIdx.x, ty = threadIdx.y;   // 32 x 8
    const float* ph = in + (long)h * K * N;

    #pragma unroll
    for (int j = 0; j < 32; j += 8)
        tile[ty + j][tx] = ph[(long)(k0 + ty + j) * N + n0 + tx];
    __syncthreads();

    const long ob = (long)h * N * K;
    #pragma unroll
    for (int j = 0; j < 32; j += 8) {
        const float v = tile[tx][ty + j];
        const __nv_bfloat16 hv = __float2bfloat16_rn(v);
        const long o = ob + (long)(n0 + ty + j) * K + k0 + tx;
        outh[o] = hv;
        outl[o] = __float2bfloat16_rn(v - __bfloat162float(hv));
    }
}

// ---------------- fused attention + aggregation (round-8 proven; hi/lo output) ----------------
template <int F>
__global__ __launch_bounds__(256)
void gat_attn(const float* __restrict__ xsA, const float* __restrict__ xnA, int SA, int nA,
              const float* __restrict__ xsB, const float* __restrict__ xnB, int SB,
              const float* __restrict__ a_self, const float* __restrict__ a_neigh,
              __nv_bfloat16* __restrict__ yh, __nv_bfloat16* __restrict__ yl)
{
    constexpr int RCAP = (F == 256) ? 26 : 11;
    extern __shared__ float sm[];
    float* sx     = sm;
    float* slog   = sm + RCAP * F;
    float* slself = slog + RCAP * 4;

    const int tid = threadIdx.x;
    const int w = tid >> 5, l = tid & 31;
    const int item = blockIdx.x;

    const float* xs; const float* xn; int S;
    if (item < nA) { xs = xsA + (long)item * F;        xn = xnA + (long)item * SA * F;        S = SA; }
    else           { int b = item - nA;
                     xs = xsB + (long)b * F;           xn = xnB + (long)b * SB * F;           S = SB; }

    {
        const uint32_t sx_u = smem_u32(sx);
        const float4* s4 = (const float4*)xs;
        for (int i = tid; i < F / 4; i += 256) CP16(sx_u + i * 16, s4 + i);
        const float4* n4 = (const float4*)xn;
        for (int i = tid; i < S * F / 4; i += 256) CP16(sx_u + (F / 4 + i) * 16, n4 + i);
        CP_COMMIT();
    }

    if (w == 0) {
        float sl[4] = {0.f, 0.f, 0.f, 0.f};
        for (int c = 0; c < F / 256; c++) {
            #pragma unroll
            for (int fi = 0; fi < 8; fi++) {
                const int f = c * 256 + l + fi * 32;
                const float xv = xs[f];
                sl[0] += xv * a_self[0 * F + f];
                sl[1] += xv * a_self[1 * F + f];
                sl[2] += xv * a_self[2 * F + f];
                sl[3] += xv * a_self[3 * F + f];
            }
        }
        #pragma unroll
        for (int h = 0; h < 4; h++) {
            float v = sl[h];
            #pragma unroll
            for (int o = 16; o; o >>= 1) v += __shfl_down_sync(0xffffffffu, v, o);
            if (l == 0) slself[h] = v;
        }
    }
    CP_WAIT0();
    __syncthreads();

    {
        float lg[4][4] = {};
        for (int c = 0; c < F / 256; c++) {
            float avn[4][8];
            #pragma unroll
            for (int h = 0; h < 4; h++)
                #pragma unroll
                for (int fi = 0; fi < 8; fi++)
                    avn[h][fi] = a_neigh[h * F + c * 256 + l + fi * 32];
            #pragma unroll
            for (int ti = 0; ti < 4; ti++) {
                const int tt = w + ti * 8;
                if (tt <= S) {
                    const float* row = sx + tt * F + c * 256;
                    #pragma unroll
                    for (int fi = 0; fi < 8; fi++) {
                        const float xv = row[l + fi * 32];
                        lg[ti][0] += xv * avn[0][fi];
                        lg[ti][1] += xv * avn[1][fi];
                        lg[ti][2] += xv * avn[2][fi];
                        lg[ti][3] += xv * avn[3][fi];
                    }
                }
            }
        }
        #pragma unroll
        for (int ti = 0; ti < 4; ti++) {
            const int tt = w + ti * 8;
            #pragma unroll
            for (int h = 0; h < 4; h++) {
                float v = lg[ti][h];
                #pragma unroll
                for (int o = 16; o; o >>= 1) v += __shfl_down_sync(0xffffffffu, v, o);
                if (l == 0 && tt <= S) slog[tt * 4 + h] = v;
            }
        }
    }
    __syncthreads();

    if (tid < 32) {
        const bool act = (l <= S);
        float z[4];
        #pragma unroll
        for (int h = 0; h < 4; h++) {
            float v = act ? (slself[h] + slog[l * 4 + h]) : -1e30f;
            z[h] = (v >= 0.f) ? v : NEG_SLOPE * v;
        }
        #pragma unroll
        for (int h = 0; h < 4; h++) {
            float m = z[h];
            #pragma unroll
            for (int o = 16; o; o >>= 1) m = fmaxf(m, __shfl_xor_sync(0xffffffffu, m, o));
            const float ev = act ? __expf(z[h] - m) : 0.f;
            float s = ev;
            #pragma unroll
            for (int o = 16; o; o >>= 1) s += __shfl_xor_sync(0xffffffffu, s, o);
            if (act) slog[l * 4 + h] = ev / s;
        }
    }
    __syncthreads();

    __nv_bfloat16* yoh = yh + (long)item * NHEAD * F;
    __nv_bfloat16* yol = yl + (long)item * NHEAD * F;
    for (int f = tid; f < F; f += 256) {
        float a[4] = {0.f, 0.f, 0.f, 0.f};
        for (int s = 0; s <= S; s++) {
            const float xv = sx[s * F + f];
            const float4 at = *(const float4*)(slog + s * 4);
            a[0] += at.x * xv; a[1] += at.y * xv; a[2] += at.z * xv; a[3] += at.w * xv;
        }
        #pragma unroll
        for (int h = 0; h < 4; h++) {
            const __nv_bfloat16 hv = __float2bfloat16_rn(a[h]);
            yoh[h * F + f] = hv;
            yol[h * F + f] = __float2bfloat16_rn(a[h] - __bfloat162float(hv));
        }
    }
}

// ---------------- 4-way partial reduce ----------------
__global__ void reduce4(const float4* __restrict__ p, float4* __restrict__ out, int n4)
{
    const int i = blockIdx.x * blockDim.x + threadIdx.x;
    if (i < n4) {
        float4 a = p[i], b = p[i + n4], c = p[i + 2 * n4], d = p[i + 3 * n4];
        out[i] = make_float4(a.x + b.x + c.x + d.x, a.y + b.y + c.y + d.y,
                             a.z + b.z + c.z + d.z, a.w + b.w + c.w + d.w);
    }
}

// ---------------- launch ----------------
template <typename T>
static T* sym_addr(const void* symbol)
{
    void* p = nullptr;
    cudaGetSymbolAddress(&p, symbol);
    return (T*)p;
}

extern "C" void kernel_launch(void* const* d_in, const int* in_sizes, int n_in,
                              void* d_out, int out_size)
{
    const float* x0  = (const float*)d_in[0];
    const float* x1  = (const float*)d_in[1];
    const float* x2  = (const float*)d_in[2];
    const float* w0  = (const float*)d_in[3];
    const float* a0s = (const float*)d_in[4];
    const float* a0n = (const float*)d_in[5];
    const float* w1  = (const float*)d_in[6];
    const float* a1s = (const float*)d_in[7];
    const float* a1n = (const float*)d_in[8];
    const float* fcw = (const float*)d_in[9];
    float* out = (float*)d_out;

    const int Bn   = in_sizes[0] / 256;        // 1024
    const int nA   = Bn * 10;                  // 10240
    const int nTot = nA + Bn;                  // 11264

    __nv_bfloat16* yh   = sym_addr<__nv_bfloat16>(g_yh);
    __nv_bfloat16* yl   = sym_addr<__nv_bfloat16>(g_yl);
    float*         hb   = sym_addr<float>(g_h);
    __nv_bfloat16* y2h  = sym_addr<__nv_bfloat16>(g_y2h);
    __nv_bfloat16* y2l  = sym_addr<__nv_bfloat16>(g_y2l);
    float*         W2   = sym_addr<float>(g_W2);
    __nv_bfloat16* Wt2h = sym_addr<__nv_bfloat16>(g_Wt2h);
    __nv_bfloat16* Wt2l = sym_addr<__nv_bfloat16>(g_Wt2l);
    __nv_bfloat16* Wt0h = sym_addr<__nv_bfloat16>(g_Wt0h);
    __nv_bfloat16* Wt0l = sym_addr<__nv_bfloat16>(g_Wt0l);
    float*         part = sym_addr<float>(g_part);

    const int smemB = (2 * 64 + 2 * 128) * LRow * 2;   // 55296 bytes
    cudaFuncSetAttribute(gemm_hmma, cudaFuncAttributeMaxDynamicSharedMemorySize, smemB);
    cudaFuncSetAttribute(gemm_hmma_pre, cudaFuncAttributeMaxDynamicSharedMemorySize, smemB);

    // ---- W2 fold: W2[h] = w1[h] @ fcw[h*128:(h+1)*128, :]  (f32) ----
    gemm_hmma<<<dim3(8, 2, NHEAD), 256, smemB>>>(
        w1, fcw, W2, 128,
        128, (long)512 * 128,
        256, (long)128 * 256,
        256, (long)512 * 256);

    // ---- weight transposes + splits ----
    transpose_split<<<dim3(16, 8, NHEAD), dim3(32, 8)>>>(W2, Wt2h, Wt2l, 512, 256);
    transpose_split<<<dim3(8, 4, NHEAD), dim3(32, 8)>>>(w0, Wt0h, Wt0l, 256, 128);

    // ---- layer-0 attention (round-8 form), hi/lo bf16 output ----
    {
        const size_t smem = (size_t)(26 * 256 + 26 * 4 + 8) * sizeof(float);
        gat_attn<256><<<nTot, 256, smem>>>(x1, x2, 25, nA,
                                           x0, x1, 10,
                                           a0s, a0n, yh, yl);
    }

    // ---- layer-0 projection: hb = y @ w0 per head  (pre-split HMMA) ----
    gemm_hmma_pre<<<dim3(nTot / 64, 1, NHEAD), 256, smemB>>>(
        yh, yl, Wt0h, Wt0l, hb, 256,
        /*lda*/1024, /*aHead*/256, /*wHead*/(long)128 * 256,
        /*ldc*/512, /*cHead*/128);

    // ---- layer-1 attention, hi/lo bf16 output ----
    {
        const size_t smem = (size_t)(11 * 512 + 11 * 4 + 8) * sizeof(float);
        gat_attn<512><<<Bn, 256, smem>>>(hb + (long)nA * 512, hb, 10, Bn,
                                         hb + (long)nA * 512, hb, 10,
                                         a1s, a1n, y2h, y2l);
    }

    // ---- folded back-end: part[h] = y2[:,h,:] @ W2[h]  (pre-split HMMA) ----
    gemm_hmma_pre<<<dim3(Bn / 64, 2, NHEAD), 256, smemB>>>(
        y2h, y2l, Wt2h, Wt2l, part, 512,
        /*lda*/2048, /*aHead*/512, /*wHead*/(long)256 * 512,
        /*ldc*/256, /*cHead*/(long)Bn * 256);

    // ---- out = sum over heads ----
    const int n4 = Bn * 256 / 4;
    reduce4<<<(n4 + 255) / 256, 256>>>((const float4*)part, (float4*)out, n4);
}